// round 15
// baseline (speedup 1.0000x reference)
#include <cuda_runtime.h>
#include <math.h>

// ---------------------------------------------------------------------------
// MS-SSIM + L1 loss — champion R14 (243.9us) with the final combine folded
// into fusedK's last-finishing block (single launch).
//
// Coefs: compile-time-immediate Gaussian taps (constexpr exp, sub-FLT_MIN
// flushed to 0 — bit-faithful to the reference's float32 mask build).
// Packed paths use MOV-imm + FFMA2, scalar paths FFMA-imm. No coef memory.
//
// fusedK per 64x64 tile (512 thr, 96x96 slab), per (channel,sigma) combo:
//   hP(x)->sync->vP->sync->hP(y)->sync->vP->sync->{carrierXY | scalar xy}
//   packed (v,v^2) FFMA2 convs; carrier = (x*y,|x-y|) dual conv;
//   immediate fold, prod/l1s in registers; block reduce -> partials.
// Last block (atomic counter, self-resetting for graph replay) computes
// disc MSE + deterministic fixed-order final combine -> out[0].
// ---------------------------------------------------------------------------

typedef unsigned long long u64;

#define W2 97     // slab row stride (floats); conflict-free
#define WTU 65    // tmp row stride (u64 packed / float scalar)
#define NT 512
#define NBLK 512
#define SMEM_BYTES (2 * 96 * W2 * 4 + 96 * WTU * 8)   // 124416

__device__ float g_partLoss[NBLK];
__device__ float g_partL1[NBLK];
__device__ int g_counter;   // zero-init; self-reset each launch

// ------------------------- compile-time Gaussian ---------------------------
__host__ __device__ constexpr double cexp(double x) {
    // x <= 0. exp(x) = 2^n * e^r, r in [0, ln2).
    constexpr double LN2 = 0.6931471805599453;
    double q = x / LN2;
    long long n = (long long)q;
    if ((double)n > q) n -= 1;
    double r = x - (double)n * LN2;
    double t = 1.0, sm = 1.0;
    for (int i = 1; i <= 20; i++) { t *= r / (double)i; sm += t; }
    for (long long i = 0; i > n; i--) sm *= 0.5;
    return sm;
}
__host__ __device__ constexpr double sigOf(int s) {
    return s == 0 ? 0.5 : s == 1 ? 1.0 : s == 2 ? 2.0 : s == 3 ? 4.0 : 8.0;
}
__host__ __device__ constexpr double gsum(double sig) {
    double s = 0.0;
    for (int i = 0; i < 33; i++) {
        double d = (double)(i - 16);
        s += cexp(-d * d / (2.0 * sig * sig));
    }
    return s;
}
// Normalized tap; flush sub-FLT_MIN tails to 0 (reference masks are float32,
// where these tails underflow to exactly 0 as well).
__host__ __device__ constexpr float gcoef(int s, int k) {
    double sig = sigOf(s);
    double d = (double)(k - 16);
    double v = cexp(-d * d / (2.0 * sig * sig)) / gsum(sig);
    return (v < 1.2e-38) ? 0.0f : (float)v;
}
template <int S, int K>
struct GC { static constexpr float v = gcoef(S, K); };

// ---------------------------------------------------------------------------
__device__ __forceinline__ u64 pk2(float lo, float hi) {
    u64 r; asm("mov.b64 %0, {%1, %2};" : "=l"(r) : "f"(lo), "f"(hi)); return r;
}
__device__ __forceinline__ void upk2(u64 v, float& lo, float& hi) {
    asm("mov.b64 {%0, %1}, %2;" : "=f"(lo), "=f"(hi) : "l"(v));
}
__device__ __forceinline__ u64 ffma2(u64 a, u64 b, u64 c) {
    u64 d; asm("fma.rn.f32x2 %0, %1, %2, %3;" : "=l"(d) : "l"(a), "l"(b), "l"(c));
    return d;
}

// ------------------------- h slot bodies (grp8) ----------------------------
// Packed (v, v^2), immediate coefs.
template <int S, int R, int K>
__device__ __forceinline__ void tapP(const float* __restrict__ p,
                                     u64 (&w)[8], u64 (&acc)[8]) {
    if constexpr (K <= 2 * R) {
        constexpr float gk = GC<S, 16 - R + K>::v;
        u64 c2 = pk2(gk, gk);
#pragma unroll
        for (int i = 0; i < 8; i++) acc[i] = ffma2(c2, w[(K + i) & 7], acc[i]);
        if constexpr (K < 2 * R) { float f = p[K + 8]; w[K & 7] = pk2(f, f * f); }
        tapP<S, R, K + 1>(p, w, acc);
    }
}
template <int S, int R>
__device__ __forceinline__ void hPslot(int slot, const float* __restrict__ s, u64* t) {
    int r = slot % 96, gq = slot / 96;
    const float* p = s + r * W2 + gq * 8 + (16 - R);
    u64 acc[8], w[8];
#pragma unroll
    for (int j = 0; j < 8; j++) { float f = p[j]; w[j] = pk2(f, f * f); }
#pragma unroll
    for (int i = 0; i < 8; i++) acc[i] = 0ULL;
    tapP<S, R, 0>(p, w, acc);
    u64* ob = t + r * WTU + gq * 8;
#pragma unroll
    for (int i = 0; i < 8; i++) ob[i] = acc[i];
}

// Scalar xy, immediate coefs (FFMA-imm).
template <int S, int R, int K>
__device__ __forceinline__ void tapS(const float* __restrict__ px,
                                     const float* __restrict__ py,
                                     float (&w)[8], float (&acc)[8]) {
    if constexpr (K <= 2 * R) {
        constexpr float gk = GC<S, 16 - R + K>::v;
#pragma unroll
        for (int i = 0; i < 8; i++) acc[i] = fmaf(gk, w[(K + i) & 7], acc[i]);
        if constexpr (K < 2 * R) w[K & 7] = px[K + 8] * py[K + 8];
        tapS<S, R, K + 1>(px, py, w, acc);
    }
}
template <int S, int R>
__device__ __forceinline__ void hSslot(int slot, const float* sx, const float* sy,
                                       float* t0) {
    int r = slot % 96, gq = slot / 96;
    const float* px = sx + r * W2 + gq * 8 + (16 - R);
    const float* py = sy + r * W2 + gq * 8 + (16 - R);
    float acc[8], w[8];
#pragma unroll
    for (int j = 0; j < 8; j++) w[j] = px[j] * py[j];
#pragma unroll
    for (int i = 0; i < 8; i++) acc[i] = 0.0f;
    tapS<S, R, 0>(px, py, w, acc);
    float* ob = t0 + r * WTU + gq * 8;
#pragma unroll
    for (int i = 0; i < 8; i++) ob[i] = acc[i];
}

// Packed (x*y, |x-y|) dual conv, full 33 taps, per-lane immediate coefs.
template <int SA, int K>
__device__ __forceinline__ void tapXY(const float* __restrict__ px,
                                      const float* __restrict__ py,
                                      u64 (&w)[8], u64 (&acc)[8]) {
    if constexpr (K <= 32) {
        constexpr float ga = GC<SA, K>::v;
        constexpr float gb = GC<4, K>::v;
        u64 c2 = pk2(ga, gb);
#pragma unroll
        for (int i = 0; i < 8; i++) acc[i] = ffma2(c2, w[(K + i) & 7], acc[i]);
        if constexpr (K < 32) {
            float xv = px[K + 8], yv = py[K + 8];
            w[K & 7] = pk2(xv * yv, fabsf(xv - yv));
        }
        tapXY<SA, K + 1>(px, py, w, acc);
    }
}
template <int SA>
__device__ __forceinline__ void hXYslot(int slot, const float* sx, const float* sy,
                                        u64* t) {
    int r = slot % 96, gq = slot / 96;
    const float* px = sx + r * W2 + gq * 8;
    const float* py = sy + r * W2 + gq * 8;
    u64 acc[8], w[8];
#pragma unroll
    for (int j = 0; j < 8; j++) {
        float xv = px[j], yv = py[j];
        w[j] = pk2(xv * yv, fabsf(xv - yv));
    }
#pragma unroll
    for (int i = 0; i < 8; i++) acc[i] = 0ULL;
    tapXY<SA, 0>(px, py, w, acc);
    u64* ob = t + r * WTU + gq * 8;
#pragma unroll
    for (int i = 0; i < 8; i++) ob[i] = acc[i];
}

// ------------------------- v passes (64 cols x 8 row-groups) ---------------
template <int S, int R, int K>
__device__ __forceinline__ void vtapP(const u64* __restrict__ p,
                                      u64 (&w)[8], u64 (&acc)[8]) {
    if constexpr (K <= 2 * R) {
        constexpr float gk = GC<S, 16 - R + K>::v;
        u64 c2 = pk2(gk, gk);
#pragma unroll
        for (int i = 0; i < 8; i++) acc[i] = ffma2(c2, w[(K + i) & 7], acc[i]);
        if constexpr (K < 2 * R) w[K & 7] = p[(K + 8) * WTU];
        vtapP<S, R, K + 1>(p, w, acc);
    }
}
template <int S, int R>
__device__ __forceinline__ void vpassP(const u64* t2, int tx, int ty, u64 (&out)[8]) {
    const u64* p = t2 + (ty * 8 + 16 - R) * WTU + tx;
    u64 acc[8], w[8];
#pragma unroll
    for (int j = 0; j < 8; j++) w[j] = p[j * WTU];
#pragma unroll
    for (int i = 0; i < 8; i++) acc[i] = 0ULL;
    vtapP<S, R, 0>(p, w, acc);
#pragma unroll
    for (int i = 0; i < 8; i++) out[i] = acc[i];
}

template <int SA, int K>
__device__ __forceinline__ void vtapXY(const u64* __restrict__ p,
                                       u64 (&w)[8], u64 (&acc)[8]) {
    if constexpr (K <= 32) {
        constexpr float ga = GC<SA, K>::v;
        constexpr float gb = GC<4, K>::v;
        u64 c2 = pk2(ga, gb);
#pragma unroll
        for (int i = 0; i < 8; i++) acc[i] = ffma2(c2, w[(K + i) & 7], acc[i]);
        if constexpr (K < 32) w[K & 7] = p[(K + 8) * WTU];
        vtapXY<SA, K + 1>(p, w, acc);
    }
}
template <int SA>
__device__ __forceinline__ void vpassXY(const u64* t2, int tx, int ty, u64 (&out)[8]) {
    const u64* p = t2 + ty * 8 * WTU + tx;
    u64 acc[8], w[8];
#pragma unroll
    for (int j = 0; j < 8; j++) w[j] = p[j * WTU];
#pragma unroll
    for (int i = 0; i < 8; i++) acc[i] = 0ULL;
    vtapXY<SA, 0>(p, w, acc);
#pragma unroll
    for (int i = 0; i < 8; i++) out[i] = acc[i];
}

template <int S, int R, int K>
__device__ __forceinline__ void vtapS(const float* __restrict__ p,
                                      float (&w)[8], float (&acc)[8]) {
    if constexpr (K <= 2 * R) {
        constexpr float gk = GC<S, 16 - R + K>::v;
#pragma unroll
        for (int i = 0; i < 8; i++) acc[i] = fmaf(gk, w[(K + i) & 7], acc[i]);
        if constexpr (K < 2 * R) w[K & 7] = p[(K + 8) * WTU];
        vtapS<S, R, K + 1>(p, w, acc);
    }
}
template <int S, int R>
__device__ __forceinline__ void vpassS(const float* t0, int tx, int ty,
                                       float (&out)[8]) {
    const float* p = t0 + (ty * 8 + 16 - R) * WTU + tx;
    float acc[8], w[8];
#pragma unroll
    for (int j = 0; j < 8; j++) w[j] = p[j * WTU];
#pragma unroll
    for (int i = 0; i < 8; i++) acc[i] = 0.0f;
    vtapS<S, R, 0>(p, w, acc);
#pragma unroll
    for (int i = 0; i < 8; i++) out[i] = acc[i];
}

// ---------------------------------------------------------------------------
template <int S, int R, bool CARRIER>
__device__ __forceinline__ void comboP(int mult, bool lm,
                                       const float* sx, const float* sy,
                                       u64* t2, int tid, int tx, int ty,
                                       float (&prod)[8], float (&l1s)[8]) {
    u64 o1[8], o2[8];
    float exy[8];

    for (int idx = tid; idx < 768; idx += NT) hPslot<S, R>(idx, sx, t2);
    __syncthreads();
    vpassP<S, R>(t2, tx, ty, o1);
    __syncthreads();
    for (int idx = tid; idx < 768; idx += NT) hPslot<S, R>(idx, sy, t2);
    __syncthreads();
    vpassP<S, R>(t2, tx, ty, o2);
    __syncthreads();

    if constexpr (CARRIER) {
        u64 o3[8];
        for (int idx = tid; idx < 768; idx += NT) hXYslot<S>(idx, sx, sy, t2);
        __syncthreads();
        vpassXY<S>(t2, tx, ty, o3);
        __syncthreads();
#pragma unroll
        for (int i = 0; i < 8; i++) {
            float lv;
            upk2(o3[i], exy[i], lv);
            l1s[i] += lv;
        }
    } else {
        float* t0 = (float*)t2;
        for (int idx = tid; idx < 768; idx += NT) hSslot<S, R>(idx, sx, sy, t0);
        __syncthreads();
        vpassS<S, R>(t0, tx, ty, exy);
        __syncthreads();
    }

#pragma unroll
    for (int i = 0; i < 8; i++) {
        float mux, ex2, muy, ey2;
        upk2(o1[i], mux, ex2);
        upk2(o2[i], muy, ey2);
        float m2x = mux * mux, m2y = muy * muy, mxy = mux * muy;
        float sxx = ex2 - m2x, syy = ey2 - m2y, sxyv = exy[i] - mxy;
        float cs = __fdividef(2.0f * sxyv + 9.0e-4f, sxx + syy + 9.0e-4f);
        float m = cs;
        if (mult >= 2) m *= cs;
        if (mult >= 3) m *= cs;
        if (lm) {
            float l = __fdividef(2.0f * mxy + 1.0e-4f, m2x + m2y + 1.0e-4f);
            m *= l * l * l;
        }
        prod[i] *= m;
    }
}

// ---------------------------------------------------------------------------
__global__ __launch_bounds__(NT) void fusedK(const float* __restrict__ x,
                                             const float* __restrict__ y,
                                             const float* __restrict__ disc,
                                             int ndisc, float* __restrict__ out) {
    extern __shared__ float smem[];
    float* sx = smem;                    // 96 x W2
    float* sy = sx + 96 * W2;
    u64* t2 = (u64*)(sy + 96 * W2);      // 96 x WTU u64

    int tid = threadIdx.x;
    int tx = tid & 63, ty = tid >> 6;
    int col0 = blockIdx.x * 64, row0 = blockIdx.y * 64, b = blockIdx.z;

    float prod[8], l1s[8];
#pragma unroll
    for (int i = 0; i < 8; i++) { prod[i] = 1.0f; l1s[i] = 0.0f; }
    float rawL1 = 0.0f;

    for (int c = 0; c < 3; c++) {
        const float* xp = x + (size_t)(b * 3 + c) * 262144;
        const float* yp = y + (size_t)(b * 3 + c) * 262144;
        __syncthreads();
        for (int idx = tid; idx < 96 * 96; idx += NT) {
            int rr = idx / 96, cc = idx - rr * 96;
            int gr = row0 - 16 + rr, gc = col0 - 16 + cc;
            float xv = 0.0f, yv = 0.0f;
            if (gr >= 0 && gr < 512 && gc >= 0 && gc < 512) {
                xv = fmaf(xp[gr * 512 + gc], 0.5f, 0.5f);
                yv = fmaf(yp[gr * 512 + gc], 0.5f, 0.5f);
            }
            sx[rr * W2 + cc] = xv;
            sy[rr * W2 + cc] = yv;
            if (rr >= 16 && rr < 80 && cc >= 16 && cc < 80)
                rawL1 += fabsf(xv - yv);
        }
        __syncthreads();

        if (c == 0) {
            comboP<0, 3, false>(3, false, sx, sy, t2, tid, tx, ty, prod, l1s);
            comboP<1, 6, true>(2, false, sx, sy, t2, tid, tx, ty, prod, l1s);
        } else if (c == 1) {
            comboP<1, 6, false>(1, false, sx, sy, t2, tid, tx, ty, prod, l1s);
            comboP<2, 11, false>(3, false, sx, sy, t2, tid, tx, ty, prod, l1s);
            comboP<3, 16, true>(1, false, sx, sy, t2, tid, tx, ty, prod, l1s);
        } else {
            comboP<3, 16, false>(2, false, sx, sy, t2, tid, tx, ty, prod, l1s);
            comboP<4, 16, true>(3, true, sx, sy, t2, tid, tx, ty, prod, l1s);
        }
    }

    float tsum = 0.0f;
#pragma unroll
    for (int i = 0; i < 8; i++) {
        float ms = 1.0f - prod[i];
        float mix = 200.0f * (0.025f * ms + 0.975f * (l1s[i] * (1.0f / 3.0f)));
        tsum += mix;
    }

    // Block reduction into partials.
    __syncthreads();
    float* r1 = (float*)t2;
    float* r2 = r1 + NT;
    r1[tid] = tsum;
    r2[tid] = rawL1;
    __syncthreads();
    for (int s = NT / 2; s > 0; s >>= 1) {
        if (tid < s) { r1[tid] += r1[tid + s]; r2[tid] += r2[tid + s]; }
        __syncthreads();
    }
    if (tid == 0) {
        int bid = (blockIdx.z * 8 + blockIdx.y) * 8 + blockIdx.x;
        g_partLoss[bid] = r1[0];
        g_partL1[bid] = r2[0];
    }

    // --- last block to finish computes the final scalar ---
    __shared__ int isLast;
    __threadfence();
    if (tid == 0) isLast = (atomicAdd(&g_counter, 1) == NBLK - 1) ? 1 : 0;
    __syncthreads();
    if (!isLast) return;
    __threadfence();   // acquire: all blocks' partials visible

    float ms = 0.0f;
    for (int i = tid; i < ndisc; i += NT) {
        float v = disc[i] - 1.0f;
        ms = fmaf(v, v, ms);
    }
    // NBLK == NT: one partial per thread, fixed order -> deterministic.
    double s1 = (double)g_partLoss[tid];
    double s2 = (double)g_partL1[tid];

    double* d1 = (double*)t2;            // reuse smem (all prior reads done)
    double* d2 = d1 + NT;
    float* d3 = (float*)(d2 + NT);
    __syncthreads();
    d1[tid] = s1; d2[tid] = s2; d3[tid] = ms;
    __syncthreads();
    for (int s = NT / 2; s > 0; s >>= 1) {
        if (tid < s) {
            d1[tid] += d1[tid + s];
            d2[tid] += d2[tid + s];
            d3[tid] += d3[tid + s];
        }
        __syncthreads();
    }
    if (tid == 0) {
        double lossMixMean = d1[0] / 2097152.0;     // 8*512*512
        double l1Mean = d2[0] / 6291456.0;          // 8*3*512*512
        double mseMean = (double)d3[0] / (double)ndisc;
        out[0] = (float)((lossMixMean + 100.0 * l1Mean + mseMean) * 0.5);
        g_counter = 0;                    // reset for next graph replay
        __threadfence();
    }
}

// ---------------------------------------------------------------------------
extern "C" void kernel_launch(void* const* d_in, const int* in_sizes, int n_in,
                              void* d_out, int out_size) {
    const float* x = (const float*)d_in[0];
    const float* y = (const float*)d_in[1];
    const float* disc = (const float*)d_in[2];
    int ndisc = in_sizes[2];

    cudaFuncSetAttribute(fusedK, cudaFuncAttributeMaxDynamicSharedMemorySize,
                         SMEM_BYTES);
    fusedK<<<dim3(8, 8, 8), NT, SMEM_BYTES>>>(x, y, disc, ndisc,
                                              (float*)d_out);
}

// round 16
// speedup vs baseline: 1.0161x; 1.0161x over previous
#include <cuda_runtime.h>
#include <math.h>

// ---------------------------------------------------------------------------
// MS-SSIM + L1 loss — champion R14 (243.9us) + distributed disc-MSE.
//
// Two launches (R15 proved fusing the final combine into fusedK slows the
// hot kernel): fusedK computes everything per-tile INCLUDING a one-element-
// per-thread disc MSE partial (j = bid + 512*tid; uniform, deterministic),
// finalK (512 thr) sums 3x512 partials in fixed order -> scalar.
//
// Coefs: compile-time-immediate Gaussian taps (constexpr exp, sub-FLT_MIN
// flushed to 0 — bit-faithful to the reference's float32 mask build).
// Packed conv paths use MOV-imm + FFMA2, scalar paths FFMA-imm.
//
// fusedK per 64x64 tile (512 thr, 96x96 slab), per (channel,sigma) combo:
//   hP(x)->sync->vP->sync->hP(y)->sync->vP->sync->{carrierXY | scalar xy}
//   packed (v,v^2) FFMA2 convs; carrier = (x*y,|x-y|) dual conv;
//   immediate fold, prod/l1s in registers; block reduce -> partials.
// ---------------------------------------------------------------------------

typedef unsigned long long u64;

#define W2 97     // slab row stride (floats); conflict-free
#define WTU 65    // tmp row stride (u64 packed / float scalar)
#define NT 512
#define NBLK 512
#define SMEM_BYTES (2 * 96 * W2 * 4 + 96 * WTU * 8)   // 124416

__device__ float g_partLoss[NBLK];
__device__ float g_partL1[NBLK];
__device__ float g_partMSE[NBLK];

// ------------------------- compile-time Gaussian ---------------------------
__host__ __device__ constexpr double cexp(double x) {
    // x <= 0. exp(x) = 2^n * e^r, r in [0, ln2).
    constexpr double LN2 = 0.6931471805599453;
    double q = x / LN2;
    long long n = (long long)q;
    if ((double)n > q) n -= 1;
    double r = x - (double)n * LN2;
    double t = 1.0, sm = 1.0;
    for (int i = 1; i <= 20; i++) { t *= r / (double)i; sm += t; }
    for (long long i = 0; i > n; i--) sm *= 0.5;
    return sm;
}
__host__ __device__ constexpr double sigOf(int s) {
    return s == 0 ? 0.5 : s == 1 ? 1.0 : s == 2 ? 2.0 : s == 3 ? 4.0 : 8.0;
}
__host__ __device__ constexpr double gsum(double sig) {
    double s = 0.0;
    for (int i = 0; i < 33; i++) {
        double d = (double)(i - 16);
        s += cexp(-d * d / (2.0 * sig * sig));
    }
    return s;
}
// Normalized tap; flush sub-FLT_MIN tails to 0 (reference masks are float32,
// where these tails underflow to exactly 0 as well).
__host__ __device__ constexpr float gcoef(int s, int k) {
    double sig = sigOf(s);
    double d = (double)(k - 16);
    double v = cexp(-d * d / (2.0 * sig * sig)) / gsum(sig);
    return (v < 1.2e-38) ? 0.0f : (float)v;
}
template <int S, int K>
struct GC { static constexpr float v = gcoef(S, K); };

// ---------------------------------------------------------------------------
__device__ __forceinline__ u64 pk2(float lo, float hi) {
    u64 r; asm("mov.b64 %0, {%1, %2};" : "=l"(r) : "f"(lo), "f"(hi)); return r;
}
__device__ __forceinline__ void upk2(u64 v, float& lo, float& hi) {
    asm("mov.b64 {%0, %1}, %2;" : "=f"(lo), "=f"(hi) : "l"(v));
}
__device__ __forceinline__ u64 ffma2(u64 a, u64 b, u64 c) {
    u64 d; asm("fma.rn.f32x2 %0, %1, %2, %3;" : "=l"(d) : "l"(a), "l"(b), "l"(c));
    return d;
}

// ------------------------- h slot bodies (grp8) ----------------------------
// Packed (v, v^2), immediate coefs.
template <int S, int R, int K>
__device__ __forceinline__ void tapP(const float* __restrict__ p,
                                     u64 (&w)[8], u64 (&acc)[8]) {
    if constexpr (K <= 2 * R) {
        constexpr float gk = GC<S, 16 - R + K>::v;
        u64 c2 = pk2(gk, gk);
#pragma unroll
        for (int i = 0; i < 8; i++) acc[i] = ffma2(c2, w[(K + i) & 7], acc[i]);
        if constexpr (K < 2 * R) { float f = p[K + 8]; w[K & 7] = pk2(f, f * f); }
        tapP<S, R, K + 1>(p, w, acc);
    }
}
template <int S, int R>
__device__ __forceinline__ void hPslot(int slot, const float* __restrict__ s, u64* t) {
    int r = slot % 96, gq = slot / 96;
    const float* p = s + r * W2 + gq * 8 + (16 - R);
    u64 acc[8], w[8];
#pragma unroll
    for (int j = 0; j < 8; j++) { float f = p[j]; w[j] = pk2(f, f * f); }
#pragma unroll
    for (int i = 0; i < 8; i++) acc[i] = 0ULL;
    tapP<S, R, 0>(p, w, acc);
    u64* ob = t + r * WTU + gq * 8;
#pragma unroll
    for (int i = 0; i < 8; i++) ob[i] = acc[i];
}

// Scalar xy, immediate coefs (FFMA-imm).
template <int S, int R, int K>
__device__ __forceinline__ void tapS(const float* __restrict__ px,
                                     const float* __restrict__ py,
                                     float (&w)[8], float (&acc)[8]) {
    if constexpr (K <= 2 * R) {
        constexpr float gk = GC<S, 16 - R + K>::v;
#pragma unroll
        for (int i = 0; i < 8; i++) acc[i] = fmaf(gk, w[(K + i) & 7], acc[i]);
        if constexpr (K < 2 * R) w[K & 7] = px[K + 8] * py[K + 8];
        tapS<S, R, K + 1>(px, py, w, acc);
    }
}
template <int S, int R>
__device__ __forceinline__ void hSslot(int slot, const float* sx, const float* sy,
                                       float* t0) {
    int r = slot % 96, gq = slot / 96;
    const float* px = sx + r * W2 + gq * 8 + (16 - R);
    const float* py = sy + r * W2 + gq * 8 + (16 - R);
    float acc[8], w[8];
#pragma unroll
    for (int j = 0; j < 8; j++) w[j] = px[j] * py[j];
#pragma unroll
    for (int i = 0; i < 8; i++) acc[i] = 0.0f;
    tapS<S, R, 0>(px, py, w, acc);
    float* ob = t0 + r * WTU + gq * 8;
#pragma unroll
    for (int i = 0; i < 8; i++) ob[i] = acc[i];
}

// Packed (x*y, |x-y|) dual conv, full 33 taps, per-lane immediate coefs.
template <int SA, int K>
__device__ __forceinline__ void tapXY(const float* __restrict__ px,
                                      const float* __restrict__ py,
                                      u64 (&w)[8], u64 (&acc)[8]) {
    if constexpr (K <= 32) {
        constexpr float ga = GC<SA, K>::v;
        constexpr float gb = GC<4, K>::v;
        u64 c2 = pk2(ga, gb);
#pragma unroll
        for (int i = 0; i < 8; i++) acc[i] = ffma2(c2, w[(K + i) & 7], acc[i]);
        if constexpr (K < 32) {
            float xv = px[K + 8], yv = py[K + 8];
            w[K & 7] = pk2(xv * yv, fabsf(xv - yv));
        }
        tapXY<SA, K + 1>(px, py, w, acc);
    }
}
template <int SA>
__device__ __forceinline__ void hXYslot(int slot, const float* sx, const float* sy,
                                        u64* t) {
    int r = slot % 96, gq = slot / 96;
    const float* px = sx + r * W2 + gq * 8;
    const float* py = sy + r * W2 + gq * 8;
    u64 acc[8], w[8];
#pragma unroll
    for (int j = 0; j < 8; j++) {
        float xv = px[j], yv = py[j];
        w[j] = pk2(xv * yv, fabsf(xv - yv));
    }
#pragma unroll
    for (int i = 0; i < 8; i++) acc[i] = 0ULL;
    tapXY<SA, 0>(px, py, w, acc);
    u64* ob = t + r * WTU + gq * 8;
#pragma unroll
    for (int i = 0; i < 8; i++) ob[i] = acc[i];
}

// ------------------------- v passes (64 cols x 8 row-groups) ---------------
template <int S, int R, int K>
__device__ __forceinline__ void vtapP(const u64* __restrict__ p,
                                      u64 (&w)[8], u64 (&acc)[8]) {
    if constexpr (K <= 2 * R) {
        constexpr float gk = GC<S, 16 - R + K>::v;
        u64 c2 = pk2(gk, gk);
#pragma unroll
        for (int i = 0; i < 8; i++) acc[i] = ffma2(c2, w[(K + i) & 7], acc[i]);
        if constexpr (K < 2 * R) w[K & 7] = p[(K + 8) * WTU];
        vtapP<S, R, K + 1>(p, w, acc);
    }
}
template <int S, int R>
__device__ __forceinline__ void vpassP(const u64* t2, int tx, int ty, u64 (&out)[8]) {
    const u64* p = t2 + (ty * 8 + 16 - R) * WTU + tx;
    u64 acc[8], w[8];
#pragma unroll
    for (int j = 0; j < 8; j++) w[j] = p[j * WTU];
#pragma unroll
    for (int i = 0; i < 8; i++) acc[i] = 0ULL;
    vtapP<S, R, 0>(p, w, acc);
#pragma unroll
    for (int i = 0; i < 8; i++) out[i] = acc[i];
}

template <int SA, int K>
__device__ __forceinline__ void vtapXY(const u64* __restrict__ p,
                                       u64 (&w)[8], u64 (&acc)[8]) {
    if constexpr (K <= 32) {
        constexpr float ga = GC<SA, K>::v;
        constexpr float gb = GC<4, K>::v;
        u64 c2 = pk2(ga, gb);
#pragma unroll
        for (int i = 0; i < 8; i++) acc[i] = ffma2(c2, w[(K + i) & 7], acc[i]);
        if constexpr (K < 32) w[K & 7] = p[(K + 8) * WTU];
        vtapXY<SA, K + 1>(p, w, acc);
    }
}
template <int SA>
__device__ __forceinline__ void vpassXY(const u64* t2, int tx, int ty, u64 (&out)[8]) {
    const u64* p = t2 + ty * 8 * WTU + tx;
    u64 acc[8], w[8];
#pragma unroll
    for (int j = 0; j < 8; j++) w[j] = p[j * WTU];
#pragma unroll
    for (int i = 0; i < 8; i++) acc[i] = 0ULL;
    vtapXY<SA, 0>(p, w, acc);
#pragma unroll
    for (int i = 0; i < 8; i++) out[i] = acc[i];
}

template <int S, int R, int K>
__device__ __forceinline__ void vtapS(const float* __restrict__ p,
                                      float (&w)[8], float (&acc)[8]) {
    if constexpr (K <= 2 * R) {
        constexpr float gk = GC<S, 16 - R + K>::v;
#pragma unroll
        for (int i = 0; i < 8; i++) acc[i] = fmaf(gk, w[(K + i) & 7], acc[i]);
        if constexpr (K < 2 * R) w[K & 7] = p[(K + 8) * WTU];
        vtapS<S, R, K + 1>(p, w, acc);
    }
}
template <int S, int R>
__device__ __forceinline__ void vpassS(const float* t0, int tx, int ty,
                                       float (&out)[8]) {
    const float* p = t0 + (ty * 8 + 16 - R) * WTU + tx;
    float acc[8], w[8];
#pragma unroll
    for (int j = 0; j < 8; j++) w[j] = p[j * WTU];
#pragma unroll
    for (int i = 0; i < 8; i++) acc[i] = 0.0f;
    vtapS<S, R, 0>(p, w, acc);
#pragma unroll
    for (int i = 0; i < 8; i++) out[i] = acc[i];
}

// ---------------------------------------------------------------------------
template <int S, int R, bool CARRIER>
__device__ __forceinline__ void comboP(int mult, bool lm,
                                       const float* sx, const float* sy,
                                       u64* t2, int tid, int tx, int ty,
                                       float (&prod)[8], float (&l1s)[8]) {
    u64 o1[8], o2[8];
    float exy[8];

    for (int idx = tid; idx < 768; idx += NT) hPslot<S, R>(idx, sx, t2);
    __syncthreads();
    vpassP<S, R>(t2, tx, ty, o1);
    __syncthreads();
    for (int idx = tid; idx < 768; idx += NT) hPslot<S, R>(idx, sy, t2);
    __syncthreads();
    vpassP<S, R>(t2, tx, ty, o2);
    __syncthreads();

    if constexpr (CARRIER) {
        u64 o3[8];
        for (int idx = tid; idx < 768; idx += NT) hXYslot<S>(idx, sx, sy, t2);
        __syncthreads();
        vpassXY<S>(t2, tx, ty, o3);
        __syncthreads();
#pragma unroll
        for (int i = 0; i < 8; i++) {
            float lv;
            upk2(o3[i], exy[i], lv);
            l1s[i] += lv;
        }
    } else {
        float* t0 = (float*)t2;
        for (int idx = tid; idx < 768; idx += NT) hSslot<S, R>(idx, sx, sy, t0);
        __syncthreads();
        vpassS<S, R>(t0, tx, ty, exy);
        __syncthreads();
    }

#pragma unroll
    for (int i = 0; i < 8; i++) {
        float mux, ex2, muy, ey2;
        upk2(o1[i], mux, ex2);
        upk2(o2[i], muy, ey2);
        float m2x = mux * mux, m2y = muy * muy, mxy = mux * muy;
        float sxx = ex2 - m2x, syy = ey2 - m2y, sxyv = exy[i] - mxy;
        float cs = __fdividef(2.0f * sxyv + 9.0e-4f, sxx + syy + 9.0e-4f);
        float m = cs;
        if (mult >= 2) m *= cs;
        if (mult >= 3) m *= cs;
        if (lm) {
            float l = __fdividef(2.0f * mxy + 1.0e-4f, m2x + m2y + 1.0e-4f);
            m *= l * l * l;
        }
        prod[i] *= m;
    }
}

// ---------------------------------------------------------------------------
__global__ __launch_bounds__(NT) void fusedK(const float* __restrict__ x,
                                             const float* __restrict__ y,
                                             const float* __restrict__ disc,
                                             int ndisc) {
    extern __shared__ float smem[];
    float* sx = smem;                    // 96 x W2
    float* sy = sx + 96 * W2;
    u64* t2 = (u64*)(sy + 96 * W2);      // 96 x WTU u64

    int tid = threadIdx.x;
    int tx = tid & 63, ty = tid >> 6;
    int col0 = blockIdx.x * 64, row0 = blockIdx.y * 64, b = blockIdx.z;
    int bid = (blockIdx.z * 8 + blockIdx.y) * 8 + blockIdx.x;

    // Distributed disc-MSE partial: element j = bid + NBLK*tid (each element
    // of disc covered exactly once across the grid; <=1 LDG per thread).
    float rawMSE = 0.0f;
    {
        int j = bid + NBLK * tid;
        if (j < ndisc) {
            float v = disc[j] - 1.0f;
            rawMSE = v * v;
        }
    }

    float prod[8], l1s[8];
#pragma unroll
    for (int i = 0; i < 8; i++) { prod[i] = 1.0f; l1s[i] = 0.0f; }
    float rawL1 = 0.0f;

    for (int c = 0; c < 3; c++) {
        const float* xp = x + (size_t)(b * 3 + c) * 262144;
        const float* yp = y + (size_t)(b * 3 + c) * 262144;
        __syncthreads();
        for (int idx = tid; idx < 96 * 96; idx += NT) {
            int rr = idx / 96, cc = idx - rr * 96;
            int gr = row0 - 16 + rr, gc = col0 - 16 + cc;
            float xv = 0.0f, yv = 0.0f;
            if (gr >= 0 && gr < 512 && gc >= 0 && gc < 512) {
                xv = fmaf(xp[gr * 512 + gc], 0.5f, 0.5f);
                yv = fmaf(yp[gr * 512 + gc], 0.5f, 0.5f);
            }
            sx[rr * W2 + cc] = xv;
            sy[rr * W2 + cc] = yv;
            if (rr >= 16 && rr < 80 && cc >= 16 && cc < 80)
                rawL1 += fabsf(xv - yv);
        }
        __syncthreads();

        if (c == 0) {
            comboP<0, 3, false>(3, false, sx, sy, t2, tid, tx, ty, prod, l1s);
            comboP<1, 6, true>(2, false, sx, sy, t2, tid, tx, ty, prod, l1s);
        } else if (c == 1) {
            comboP<1, 6, false>(1, false, sx, sy, t2, tid, tx, ty, prod, l1s);
            comboP<2, 11, false>(3, false, sx, sy, t2, tid, tx, ty, prod, l1s);
            comboP<3, 16, true>(1, false, sx, sy, t2, tid, tx, ty, prod, l1s);
        } else {
            comboP<3, 16, false>(2, false, sx, sy, t2, tid, tx, ty, prod, l1s);
            comboP<4, 16, true>(3, true, sx, sy, t2, tid, tx, ty, prod, l1s);
        }
    }

    float tsum = 0.0f;
#pragma unroll
    for (int i = 0; i < 8; i++) {
        float ms = 1.0f - prod[i];
        float mix = 200.0f * (0.025f * ms + 0.975f * (l1s[i] * (1.0f / 3.0f)));
        tsum += mix;
    }

    // Block reduction into partials (loss, rawL1, rawMSE).
    __syncthreads();
    float* r1 = (float*)t2;
    float* r2 = r1 + NT;
    float* r3 = r2 + NT;
    r1[tid] = tsum;
    r2[tid] = rawL1;
    r3[tid] = rawMSE;
    __syncthreads();
    for (int s = NT / 2; s > 0; s >>= 1) {
        if (tid < s) {
            r1[tid] += r1[tid + s];
            r2[tid] += r2[tid + s];
            r3[tid] += r3[tid + s];
        }
        __syncthreads();
    }
    if (tid == 0) {
        g_partLoss[bid] = r1[0];
        g_partL1[bid] = r2[0];
        g_partMSE[bid] = r3[0];
    }
}

// ---------------------------------------------------------------------------
__global__ __launch_bounds__(NT) void finalK(float* out, int ndisc) {
    int tid = threadIdx.x;
    // NBLK == NT: one partial per thread, fixed order -> deterministic.
    double s1 = (double)g_partLoss[tid];
    double s2 = (double)g_partL1[tid];
    double s3 = (double)g_partMSE[tid];

    __shared__ double r1[NT], r2[NT], r3[NT];
    r1[tid] = s1; r2[tid] = s2; r3[tid] = s3;
    __syncthreads();
    for (int s = NT / 2; s > 0; s >>= 1) {
        if (tid < s) {
            r1[tid] += r1[tid + s];
            r2[tid] += r2[tid + s];
            r3[tid] += r3[tid + s];
        }
        __syncthreads();
    }
    if (tid == 0) {
        double lossMixMean = r1[0] / 2097152.0;     // 8*512*512
        double l1Mean = r2[0] / 6291456.0;          // 8*3*512*512
        double mseMean = r3[0] / (double)ndisc;
        out[0] = (float)((lossMixMean + 100.0 * l1Mean + mseMean) * 0.5);
    }
}

// ---------------------------------------------------------------------------
extern "C" void kernel_launch(void* const* d_in, const int* in_sizes, int n_in,
                              void* d_out, int out_size) {
    const float* x = (const float*)d_in[0];
    const float* y = (const float*)d_in[1];
    const float* disc = (const float*)d_in[2];
    int ndisc = in_sizes[2];

    cudaFuncSetAttribute(fusedK, cudaFuncAttributeMaxDynamicSharedMemorySize,
                         SMEM_BYTES);
    fusedK<<<dim3(8, 8, 8), NT, SMEM_BYTES>>>(x, y, disc, ndisc);
    finalK<<<1, NT>>>((float*)d_out, ndisc);
}